// round 2
// baseline (speedup 1.0000x reference)
#include <cuda_runtime.h>

#define NN 100000
#define DD 16
#define EE 3200000

// ---------------- device scratch (no allocations allowed) ----------------
__device__ float g_fs[NN * DD];   // feat_src for current layer
__device__ float g_fd[NN * DD];   // feat_dst for current layer
__device__ float g_rst[NN * DD];  // numerator accumulator  sum(ex * el)
__device__ float g_den[NN];       // denominator accumulator sum(ex)
__device__ float g_h2[NN * DD];   // layer-1 output / layer-2 input

// ---------------- helpers ----------------
__device__ __forceinline__ void red_add_v4(float* addr, float x, float y, float z, float w) {
    asm volatile("red.global.add.v4.f32 [%0], {%1,%2,%3,%4};"
                 :: "l"(addr), "f"(x), "f"(y), "f"(z), "f"(w) : "memory");
}

__device__ __forceinline__ float lrelu(float v, float slope) {
    return v > 0.0f ? v : slope * v;
}

// ---------------- kernels ----------------
__global__ void zero_kernel() {
    int i = blockIdx.x * blockDim.x + threadIdx.x;
    if (i < NN * DD) g_rst[i] = 0.0f;
    if (i < NN) g_den[i] = 0.0f;
}

// feat_src = h @ W_src + b_src ; feat_dst = h @ W_dst + b_dst
__global__ void transform_kernel(const float* __restrict__ h,
                                 const float* __restrict__ Ws, const float* __restrict__ bs,
                                 const float* __restrict__ Wd, const float* __restrict__ bd) {
    __shared__ float sWs[DD * DD], sWd[DD * DD], sbs[DD], sbd[DD];
    int tid = threadIdx.x;
    if (tid < DD * DD) { sWs[tid] = Ws[tid]; sWd[tid] = Wd[tid]; }
    if (tid < DD)      { sbs[tid] = bs[tid]; sbd[tid] = bd[tid]; }
    __syncthreads();

    int n = blockIdx.x * blockDim.x + tid;
    if (n >= NN) return;

    float hv[DD];
    const float4* hp = reinterpret_cast<const float4*>(h + (size_t)n * DD);
#pragma unroll
    for (int i = 0; i < 4; i++) {
        float4 v = hp[i];
        hv[4*i+0] = v.x; hv[4*i+1] = v.y; hv[4*i+2] = v.z; hv[4*i+3] = v.w;
    }

    float os[DD], od[DD];
#pragma unroll
    for (int j = 0; j < DD; j++) { os[j] = sbs[j]; od[j] = sbd[j]; }
#pragma unroll
    for (int k = 0; k < DD; k++) {
        float hk = hv[k];
#pragma unroll
        for (int j = 0; j < DD; j++) {
            os[j] = fmaf(hk, sWs[k * DD + j], os[j]);
            od[j] = fmaf(hk, sWd[k * DD + j], od[j]);
        }
    }

    float4* fsp = reinterpret_cast<float4*>(g_fs + (size_t)n * DD);
    float4* fdp = reinterpret_cast<float4*>(g_fd + (size_t)n * DD);
#pragma unroll
    for (int i = 0; i < 4; i++) {
        fsp[i] = make_float4(os[4*i], os[4*i+1], os[4*i+2], os[4*i+3]);
        fdp[i] = make_float4(od[4*i], od[4*i+1], od[4*i+2], od[4*i+3]);
    }
}

// One pass over edges: score -> exp -> RED accumulate numerator & denominator.
// NOTE: softmax max-subtraction dropped — scores are O(±8) here, exp() is safe,
// and the final ratio is mathematically identical.
__global__ void edge_kernel(const int* __restrict__ src, const int* __restrict__ dst,
                            const float* __restrict__ attn) {
    int e = blockIdx.x * blockDim.x + threadIdx.x;
    if (e >= EE) return;

    int s = src[e];
    int d = dst[e];

    const float4* ep = reinterpret_cast<const float4*>(g_fs + (size_t)s * DD);
    const float4* dp = reinterpret_cast<const float4*>(g_fd + (size_t)d * DD);
    const float4* ap = reinterpret_cast<const float4*>(attn);

    float4 el[4], ed[4], at[4];
#pragma unroll
    for (int i = 0; i < 4; i++) el[i] = ep[i];
#pragma unroll
    for (int i = 0; i < 4; i++) ed[i] = dp[i];
#pragma unroll
    for (int i = 0; i < 4; i++) at[i] = __ldg(&ap[i]);

    float score = 0.0f;
#pragma unroll
    for (int i = 0; i < 4; i++) {
        score = fmaf(lrelu(el[i].x + ed[i].x, 0.2f), at[i].x, score);
        score = fmaf(lrelu(el[i].y + ed[i].y, 0.2f), at[i].y, score);
        score = fmaf(lrelu(el[i].z + ed[i].z, 0.2f), at[i].z, score);
        score = fmaf(lrelu(el[i].w + ed[i].w, 0.2f), at[i].w, score);
    }

    float ex = __expf(score);

    atomicAdd(&g_den[d], ex);   // return value unused -> RED
    float* rb = g_rst + (size_t)d * DD;
#pragma unroll
    for (int i = 0; i < 4; i++) {
        red_add_v4(rb + 4 * i, ex * el[i].x, ex * el[i].y, ex * el[i].z, ex * el[i].w);
    }
}

// out = leaky_relu(rst / den, 0.01)
__global__ void finalize_kernel(float* __restrict__ out) {
    int n = blockIdx.x * blockDim.x + threadIdx.x;
    if (n >= NN) return;
    float den = g_den[n];
    float inv = (den > 0.0f) ? (1.0f / den) : 0.0f;
    const float4* rp = reinterpret_cast<const float4*>(g_rst + (size_t)n * DD);
    float4* op = reinterpret_cast<float4*>(out + (size_t)n * DD);
#pragma unroll
    for (int i = 0; i < 4; i++) {
        float4 r = rp[i];
        r.x = lrelu(r.x * inv, 0.01f);
        r.y = lrelu(r.y * inv, 0.01f);
        r.z = lrelu(r.z * inv, 0.01f);
        r.w = lrelu(r.w * inv, 0.01f);
        op[i] = r;
    }
}

// ---------------- launch ----------------
extern "C" void kernel_launch(void* const* d_in, const int* in_sizes, int n_in,
                              void* d_out, int out_size) {
    const float* emb    = (const float*)d_in[0];
    const int*   src1   = (const int*)  d_in[1];
    const int*   dst1   = (const int*)  d_in[2];
    const int*   src2   = (const int*)  d_in[3];
    const int*   dst2   = (const int*)  d_in[4];
    const float* W_src1 = (const float*)d_in[5];
    const float* b_src1 = (const float*)d_in[6];
    const float* W_dst1 = (const float*)d_in[7];
    const float* b_dst1 = (const float*)d_in[8];
    const float* attn1  = (const float*)d_in[9];
    const float* W_src2 = (const float*)d_in[10];
    const float* b_src2 = (const float*)d_in[11];
    const float* W_dst2 = (const float*)d_in[12];
    const float* b_dst2 = (const float*)d_in[13];
    const float* attn2  = (const float*)d_in[14];

    float* h2ptr = nullptr;
    cudaGetSymbolAddress((void**)&h2ptr, g_h2);

    const int TB = 256;
    int nodeBlocks = (NN + TB - 1) / TB;
    int zeroBlocks = (NN * DD + TB - 1) / TB;
    int edgeBlocks = (EE + TB - 1) / TB;

    // ---- layer 1 ----
    zero_kernel<<<zeroBlocks, TB>>>();
    transform_kernel<<<nodeBlocks, TB>>>(emb, W_src1, b_src1, W_dst1, b_dst1);
    edge_kernel<<<edgeBlocks, TB>>>(src1, dst1, attn1);
    finalize_kernel<<<nodeBlocks, TB>>>(h2ptr);

    // ---- layer 2 ----
    zero_kernel<<<zeroBlocks, TB>>>();
    transform_kernel<<<nodeBlocks, TB>>>(h2ptr, W_src2, b_src2, W_dst2, b_dst2);
    edge_kernel<<<edgeBlocks, TB>>>(src2, dst2, attn2);
    finalize_kernel<<<nodeBlocks, TB>>>((float*)d_out);
}